// round 4
// baseline (speedup 1.0000x reference)
#include <cuda_runtime.h>

#define BB 8
#define NN 2048
#define DD 128

// Scratch (allocation-free rule: __device__ globals)
__device__ float g_lin[BB*NN*DD];   // post-linear h
__device__ float g_nh [BB*NN*DD];   // normalized h
__device__ float g_nrm[BB*NN];      // effective norms max(||h||, eps)
__device__ float g_buf[BB*NN*DD];   // aggregated output -> next layer input

// ---------------------------------------------------------------------------
// Linear: out[r][c] = sum_k in[r][k]*W[k][c] + b[c], 64 rows per block
// ---------------------------------------------------------------------------
__global__ __launch_bounds__(256, 1)
void linear_kernel(const float* __restrict__ in, const float* __restrict__ W,
                   const float* __restrict__ bias, float* __restrict__ out) {
    extern __shared__ float sm[];
    float* sW = sm;                 // [128][128]
    float* sX = sm + DD*DD;         // [64][128]
    const int tx = threadIdx.x, ty = threadIdx.y;
    const int tid = ty*16 + tx;
    const int rowbase = blockIdx.x * 64;

    const float4* W4 = (const float4*)W;
    float4* sW4 = (float4*)sW;
#pragma unroll
    for (int i = 0; i < 16; i++) sW4[tid + i*256] = W4[tid + i*256];
    const float4* X4 = (const float4*)(in + (size_t)rowbase*DD);
    float4* sX4 = (float4*)sX;
#pragma unroll
    for (int i = 0; i < 8; i++) sX4[tid + i*256] = X4[tid + i*256];
    __syncthreads();

    float acc[4][8];
#pragma unroll
    for (int j = 0; j < 4; j++)
#pragma unroll
        for (int c = 0; c < 8; c++) acc[j][c] = 0.0f;

#pragma unroll 8
    for (int k = 0; k < DD; k++) {
        float4 w0 = *(const float4*)&sW[k*DD + tx*8];
        float4 w1 = *(const float4*)&sW[k*DD + tx*8 + 4];
#pragma unroll
        for (int j = 0; j < 4; j++) {
            float a = sX[(ty*4+j)*DD + k];
            acc[j][0] += a*w0.x; acc[j][1] += a*w0.y;
            acc[j][2] += a*w0.z; acc[j][3] += a*w0.w;
            acc[j][4] += a*w1.x; acc[j][5] += a*w1.y;
            acc[j][6] += a*w1.z; acc[j][7] += a*w1.w;
        }
    }
    float4 bv0 = *(const float4*)&bias[tx*8];
    float4 bv1 = *(const float4*)&bias[tx*8 + 4];
#pragma unroll
    for (int j = 0; j < 4; j++) {
        int row = rowbase + ty*4 + j;
        float4 o0 = make_float4(acc[j][0]+bv0.x, acc[j][1]+bv0.y,
                                acc[j][2]+bv0.z, acc[j][3]+bv0.w);
        float4 o1 = make_float4(acc[j][4]+bv1.x, acc[j][5]+bv1.y,
                                acc[j][6]+bv1.z, acc[j][7]+bv1.w);
        *(float4*)&out[(size_t)row*DD + tx*8]     = o0;
        *(float4*)&out[(size_t)row*DD + tx*8 + 4] = o1;
    }
}

// ---------------------------------------------------------------------------
// Normalize: warp per row of 128
// ---------------------------------------------------------------------------
__global__ __launch_bounds__(256, 8)
void normalize_kernel(const float* __restrict__ h, float* __restrict__ nh,
                      float* __restrict__ nrm) {
    const int tid = threadIdx.x;
    const int warp = tid >> 5, lane = tid & 31;
    const int row = blockIdx.x * 8 + warp;
    float4 v = *(const float4*)&h[(size_t)row*DD + lane*4];
    float ss = v.x*v.x + v.y*v.y + v.z*v.z + v.w*v.w;
#pragma unroll
    for (int o = 16; o; o >>= 1) ss += __shfl_xor_sync(0xffffffffu, ss, o);
    float eff = fmaxf(sqrtf(ss), 1e-12f);
    float inv = 1.0f / eff;
    float4 o4 = make_float4(v.x*inv, v.y*inv, v.z*inv, v.w*inv);
    *(float4*)&nh[(size_t)row*DD + lane*4] = o4;
    if (lane == 0) nrm[row] = eff;
}

// ---------------------------------------------------------------------------
// Fused aggregation (flash-attention style):
//   out[p][c] = sum_q ew[p][q] * (nh_p . nh_q) * nrm_q * nh_q[c]
// Block: 64 p-rows x 128 cols; loops over 32 q-tiles of 64.
// ---------------------------------------------------------------------------
__global__ __launch_bounds__(256, 1)
void aggregate_kernel(const float* __restrict__ nh, const float* __restrict__ nrm,
                      const float* __restrict__ ew, float* __restrict__ out,
                      int do_relu) {
    extern __shared__ float sm[];
    float* s_pt = sm;               // [128][65] transposed p-tile  (8320 f)
    float* s_qt = sm + 8320;        // [128][65] transposed q-tile  (8320 f)
    float* s_q  = sm + 16640;       // [64][128] row-major q-tile   (8192 f)
    float* s_S  = sm + 24832;       // [64][65]  St[q][p]           (4160 f)

    const int tx = threadIdx.x, ty = threadIdx.y;
    const int tid = ty*16 + tx;
    const int b = blockIdx.y;
    const int pbase = blockIdx.x * 64;
    const float* nh_b = nh + (size_t)b*NN*DD;

    // Load p-tile (stage row-major into s_q, transpose into s_pt)
    {
        const float4* g4 = (const float4*)(nh_b + (size_t)pbase*DD);
        float4* s4 = (float4*)s_q;
#pragma unroll
        for (int i = 0; i < 8; i++) s4[tid + i*256] = g4[tid + i*256];
    }
    __syncthreads();
#pragma unroll
    for (int i = 0; i < 32; i++) {
        int idx = tid + i*256;
        s_pt[(idx & 127)*65 + (idx >> 7)] = s_q[idx];
    }

    float acc[4][8];
#pragma unroll
    for (int j = 0; j < 4; j++)
#pragma unroll
        for (int c = 0; c < 8; c++) acc[j][c] = 0.0f;

    const float* ew_row = ew + ((size_t)b*NN + pbase)*NN;

    for (int qt = 0; qt < 32; qt++) {
        const int qbase = qt * 64;

        // prefetch edge weights + norms into registers (hidden behind compute)
        float ewr[4][4];
#pragma unroll
        for (int j = 0; j < 4; j++) {
            float4 t = *(const float4*)&ew_row[(size_t)(ty*4+j)*NN + qbase + tx*4];
            ewr[j][0] = t.x; ewr[j][1] = t.y; ewr[j][2] = t.z; ewr[j][3] = t.w;
        }
        float4 nq = *(const float4*)&nrm[(size_t)b*NN + qbase + tx*4];
        float nrmq[4] = {nq.x, nq.y, nq.z, nq.w};

        __syncthreads();   // previous PV done (protects s_q, s_S); p-transpose done (iter 0)
        {
            const float4* g4 = (const float4*)(nh_b + (size_t)qbase*DD);
            float4* s4 = (float4*)s_q;
#pragma unroll
            for (int i = 0; i < 8; i++) s4[tid + i*256] = g4[tid + i*256];
        }
        __syncthreads();
#pragma unroll
        for (int i = 0; i < 32; i++) {
            int idx = tid + i*256;
            s_qt[(idx & 127)*65 + (idx >> 7)] = s_q[idx];
        }
        __syncthreads();

        // --- S phase: sacc[i][j] = nh_q(tx*4+i) . nh_p(ty*4+j) ---
        float sacc[4][4];
#pragma unroll
        for (int i = 0; i < 4; i++)
#pragma unroll
            for (int j = 0; j < 4; j++) sacc[i][j] = 0.0f;

#pragma unroll 8
        for (int k = 0; k < 128; k++) {
            float a[4], bq[4];
#pragma unroll
            for (int j = 0; j < 4; j++) a[j]  = s_pt[k*65 + ty*4 + j];
#pragma unroll
            for (int i = 0; i < 4; i++) bq[i] = s_qt[k*65 + tx*4 + i];
#pragma unroll
            for (int i = 0; i < 4; i++)
#pragma unroll
                for (int j = 0; j < 4; j++)
                    sacc[i][j] += bq[i] * a[j];
        }

        // scale by edge weight and ||h_q||; store St[q][p]
#pragma unroll
        for (int i = 0; i < 4; i++)
#pragma unroll
            for (int j = 0; j < 4; j++)
                s_S[(tx*4+i)*65 + ty*4 + j] = sacc[i][j] * ewr[j][i] * nrmq[i];
        __syncthreads();

        // --- PV phase: acc[p][c] += St[q][p] * nh_q[q][c] ---
#pragma unroll 4
        for (int q = 0; q < 64; q++) {
            float4 v0 = *(const float4*)&s_q[q*128 + tx*8];
            float4 v1 = *(const float4*)&s_q[q*128 + tx*8 + 4];
#pragma unroll
            for (int j = 0; j < 4; j++) {
                float a = s_S[q*65 + ty*4 + j];
                acc[j][0] += a*v0.x; acc[j][1] += a*v0.y;
                acc[j][2] += a*v0.z; acc[j][3] += a*v0.w;
                acc[j][4] += a*v1.x; acc[j][5] += a*v1.y;
                acc[j][6] += a*v1.z; acc[j][7] += a*v1.w;
            }
        }
    }

    // epilogue (optional relu)
#pragma unroll
    for (int j = 0; j < 4; j++) {
        size_t row = (size_t)b*NN + pbase + ty*4 + j;
        float o[8];
#pragma unroll
        for (int c = 0; c < 8; c++)
            o[c] = do_relu ? fmaxf(acc[j][c], 0.0f) : acc[j][c];
        *(float4*)&out[row*DD + tx*8]     = make_float4(o[0], o[1], o[2], o[3]);
        *(float4*)&out[row*DD + tx*8 + 4] = make_float4(o[4], o[5], o[6], o[7]);
    }
}

// ---------------------------------------------------------------------------
extern "C" void kernel_launch(void* const* d_in, const int* in_sizes, int n_in,
                              void* d_out, int out_size) {
    const float* x  = (const float*)d_in[0];
    const float* ew = (const float*)d_in[1];
    const float* Wl[3] = {(const float*)d_in[2], (const float*)d_in[4], (const float*)d_in[6]};
    const float* bl[3] = {(const float*)d_in[3], (const float*)d_in[5], (const float*)d_in[7]};
    float* out = (float*)d_out;

    float *lin, *nhp, *nrm, *buf;
    cudaGetSymbolAddress((void**)&lin, g_lin);
    cudaGetSymbolAddress((void**)&nhp, g_nh);
    cudaGetSymbolAddress((void**)&nrm, g_nrm);
    cudaGetSymbolAddress((void**)&buf, g_buf);

    // Idempotent; first (non-captured) correctness call makes these stick.
    (void)cudaFuncSetAttribute(linear_kernel,
        cudaFuncAttributeMaxDynamicSharedMemorySize, (DD*DD + 64*DD)*4);
    (void)cudaFuncSetAttribute(aggregate_kernel,
        cudaFuncAttributeMaxDynamicSharedMemorySize, (8320+8320+8192+4160)*4);

    dim3 blk(16, 16);
    for (int l = 0; l < 3; l++) {
        const float* in = (l == 0) ? x : buf;
        linear_kernel<<<BB*NN/64, blk, (DD*DD + 64*DD)*4>>>(in, Wl[l], bl[l], lin);
        normalize_kernel<<<BB*NN/8, 256>>>(lin, nhp, nrm);
        float* o = (l == 2) ? out : buf;
        aggregate_kernel<<<dim3(NN/64, BB), blk, (8320+8320+8192+4160)*4>>>(
            nhp, nrm, ew, o, (l < 2) ? 1 : 0);
    }
}

// round 9
// speedup vs baseline: 4.6436x; 4.6436x over previous
#include <cuda_runtime.h>
#include <cuda_bf16.h>
#include <cstdint>

#define BB 8
#define NN 2048
#define DD 128

// ---------------- scratch (__device__ globals; allocation-free rule) -------
__device__ __align__(256) float g_lin[BB*NN*DD];            // post-linear h
__device__ __align__(256) float g_buf[BB*NN*DD];            // layer output
__device__ __align__(256) __nv_bfloat16 g_nh_hi[BB*NN*DD];  // normalized h, hi
__device__ __align__(256) __nv_bfloat16 g_nh_lo[BB*NN*DD];  // normalized h, lo
__device__ __align__(256) __nv_bfloat16 g_ht_hi[BB*DD*NN];  // h transposed, hi
__device__ __align__(256) __nv_bfloat16 g_ht_lo[BB*DD*NN];  // h transposed, lo

// ---------------- helpers --------------------------------------------------
__device__ __forceinline__ uint32_t smem_to_u32(const void* p) {
    uint32_t a;
    asm("{ .reg .u64 t; cvta.to.shared.u64 t, %1; cvt.u32.u64 %0, t; }"
        : "=r"(a) : "l"(p));
    return a;
}
__device__ __forceinline__ void ldsm4(uint32_t* r, uint32_t addr) {
    asm volatile("ldmatrix.sync.aligned.m8n8.x4.shared.b16 {%0,%1,%2,%3}, [%4];"
        : "=r"(r[0]), "=r"(r[1]), "=r"(r[2]), "=r"(r[3]) : "r"(addr));
}
__device__ __forceinline__ void mma16816(float* d, const uint32_t* a, const uint32_t* b) {
    asm volatile("mma.sync.aligned.m16n8k16.row.col.f32.bf16.bf16.f32 "
        "{%0,%1,%2,%3}, {%4,%5,%6,%7}, {%8,%9}, {%0,%1,%2,%3};"
        : "+f"(d[0]), "+f"(d[1]), "+f"(d[2]), "+f"(d[3])
        : "r"(a[0]), "r"(a[1]), "r"(a[2]), "r"(a[3]), "r"(b[0]), "r"(b[1]));
}
__device__ __forceinline__ uint32_t pack_hi(float f0, float f1) {
    uint32_t r;
    asm("cvt.rn.bf16x2.f32 %0, %1, %2;" : "=r"(r) : "f"(f1), "f"(f0));
    return r;
}
__device__ __forceinline__ uint32_t pack_lo(float f0, float f1, uint32_t h) {
    float g0 = __uint_as_float(h << 16);
    float g1 = __uint_as_float(h & 0xffff0000u);
    uint32_t r;
    asm("cvt.rn.bf16x2.f32 %0, %1, %2;" : "=r"(r) : "f"(f1 - g1), "f"(f0 - g0));
    return r;
}

// ---------------------------------------------------------------------------
// Linear: out[r][c] = sum_k in[r][k]*W[k][c] + b[c]
// ---------------------------------------------------------------------------
__global__ __launch_bounds__(256, 2)
void linear_kernel(const float* __restrict__ in, const float* __restrict__ W,
                   const float* __restrict__ bias, float* __restrict__ out) {
    extern __shared__ char smraw[];
    float* smf = (float*)smraw;
    float* sW = smf;
    float* sX = smf + DD*DD;
    const int tx = threadIdx.x, ty = threadIdx.y;
    const int tid = ty*16 + tx;
    const int rowbase = blockIdx.x * 64;

    const float4* W4 = (const float4*)W;
    float4* sW4 = (float4*)sW;
#pragma unroll
    for (int i = 0; i < 16; i++) sW4[tid + i*256] = W4[tid + i*256];
    const float4* X4 = (const float4*)(in + (size_t)rowbase*DD);
    float4* sX4 = (float4*)sX;
#pragma unroll
    for (int i = 0; i < 8; i++) sX4[tid + i*256] = X4[tid + i*256];
    __syncthreads();

    float acc[4][8];
#pragma unroll
    for (int j = 0; j < 4; j++)
#pragma unroll
        for (int c = 0; c < 8; c++) acc[j][c] = 0.0f;

#pragma unroll 8
    for (int k = 0; k < DD; k++) {
        float4 w0 = *(const float4*)&sW[k*DD + tx*8];
        float4 w1 = *(const float4*)&sW[k*DD + tx*8 + 4];
#pragma unroll
        for (int j = 0; j < 4; j++) {
            float a = sX[(ty*4+j)*DD + k];
            acc[j][0] += a*w0.x; acc[j][1] += a*w0.y;
            acc[j][2] += a*w0.z; acc[j][3] += a*w0.w;
            acc[j][4] += a*w1.x; acc[j][5] += a*w1.y;
            acc[j][6] += a*w1.z; acc[j][7] += a*w1.w;
        }
    }
    float4 bv0 = *(const float4*)&bias[tx*8];
    float4 bv1 = *(const float4*)&bias[tx*8 + 4];
#pragma unroll
    for (int j = 0; j < 4; j++) {
        int row = rowbase + ty*4 + j;
        *(float4*)&out[(size_t)row*DD + tx*8] =
            make_float4(acc[j][0]+bv0.x, acc[j][1]+bv0.y, acc[j][2]+bv0.z, acc[j][3]+bv0.w);
        *(float4*)&out[(size_t)row*DD + tx*8 + 4] =
            make_float4(acc[j][4]+bv1.x, acc[j][5]+bv1.y, acc[j][6]+bv1.z, acc[j][7]+bv1.w);
    }
}

// ---------------------------------------------------------------------------
// normalize_convert: per row q — nh = h/max(||h||,eps) as bf16 hi/lo (row-major)
// and h as bf16 hi/lo TRANSPOSED per batch ([b][c][q]).
// ---------------------------------------------------------------------------
__global__ __launch_bounds__(256, 4)
void normalize_convert(const float* __restrict__ h,
                       __nv_bfloat16* __restrict__ nhh, __nv_bfloat16* __restrict__ nhl,
                       __nv_bfloat16* __restrict__ hth, __nv_bfloat16* __restrict__ htl) {
    __shared__ uint32_t sh[8*64], sl[8*64];   // 8 rows x 128 bf16 (as u32 pairs)
    const int tid = threadIdx.x;
    const int w = tid >> 5, lane = tid & 31;
    const size_t rowbase = (size_t)blockIdx.x * 8;
    const size_t row = rowbase + w;

    float4 x = *(const float4*)(h + row*DD + lane*4);
    float ss = x.x*x.x + x.y*x.y + x.z*x.z + x.w*x.w;
#pragma unroll
    for (int o = 16; o; o >>= 1) ss += __shfl_xor_sync(0xffffffffu, ss, o);
    float inv = 1.0f / fmaxf(sqrtf(ss), 1e-12f);

    float n0 = x.x*inv, n1 = x.y*inv, n2 = x.z*inv, n3 = x.w*inv;
    uint32_t nha = pack_hi(n0, n1), nhb = pack_hi(n2, n3);
    uint32_t nla = pack_lo(n0, n1, nha), nlb = pack_lo(n2, n3, nhb);
    *(uint2*)(nhh + row*DD + lane*4) = make_uint2(nha, nhb);
    *(uint2*)(nhl + row*DD + lane*4) = make_uint2(nla, nlb);

    uint32_t ha = pack_hi(x.x, x.y), hb = pack_hi(x.z, x.w);
    uint32_t la = pack_lo(x.x, x.y, ha), lb = pack_lo(x.z, x.w, hb);
    sh[w*64 + lane*2] = ha; sh[w*64 + lane*2 + 1] = hb;
    sl[w*64 + lane*2] = la; sl[w*64 + lane*2 + 1] = lb;
    __syncthreads();

    const int c = tid & 127, which = tid >> 7;
    const unsigned short* s = (const unsigned short*)(which ? sl : sh);
    uint32_t p0 = (uint32_t)s[0*128 + c] | ((uint32_t)s[1*128 + c] << 16);
    uint32_t p1 = (uint32_t)s[2*128 + c] | ((uint32_t)s[3*128 + c] << 16);
    uint32_t p2 = (uint32_t)s[4*128 + c] | ((uint32_t)s[5*128 + c] << 16);
    uint32_t p3 = (uint32_t)s[6*128 + c] | ((uint32_t)s[7*128 + c] << 16);
    const size_t b = rowbase / NN, q0 = rowbase % NN;
    __nv_bfloat16* dst = which ? htl : hth;
    *(uint4*)(dst + (b*DD + c)*NN + q0) = make_uint4(p0, p1, p2, p3);
}

// ---------------------------------------------------------------------------
// aggregate_mma: out[p][c] = sum_q ew[p][q] * (nh_p . nh_q) * h[q][c]
// ldmatrix + mma.sync bf16, split hi/lo (3 products), flash over 16 q-tiles.
// ---------------------------------------------------------------------------
#define LDQ  136            // bf16 elements per smem row (padded)
#define LDQB 272            // bytes per smem row
#define SA1H 0              // persistent nh p-tile hi
#define SA1L 34816          //                      lo
#define SB1H 69632          // nh q-tile hi  (aliased: S' hi)
#define SB1L 104448         // nh q-tile lo  (aliased: S' lo)
#define SB2H 139264         // hT tile hi
#define SB2L 174080         // hT tile lo
#define SM_AGG 208896

// copy a [128 x 128] bf16 row-major tile into padded smem
__device__ __forceinline__ void g2s_tile(const __nv_bfloat16* __restrict__ g,
                                         int rs, char* s, int tid) {
#pragma unroll
    for (int i = 0; i < 8; i++) {
        int idx = tid + i*256;
        int row = idx >> 4, u = idx & 15;
        uint4 v = *(const uint4*)(g + (size_t)row*rs + u*8);
        *(uint4*)(s + row*LDQB + u*16) = v;
    }
}

// one 128x128 GEMM phase, 3-product split bf16, warp tile 32(m) x 64(n)
__device__ __forceinline__ void mma_phase(uint32_t sAhi, uint32_t sAlo,
                                          uint32_t sBhi, uint32_t sBlo,
                                          float C[2][8][4], int wm, int wn, int lane) {
    const uint32_t aoff = (uint32_t)((wm*32 + (lane & 15)) * LDQB + (lane >> 4) * 16);
    const uint32_t boff = (uint32_t)((wn*64 + (lane & 15)) * LDQB + (lane >> 4) * 16);
#pragma unroll 2
    for (int ks = 0; ks < 8; ks++) {
        const uint32_t ko = (uint32_t)(ks * 32);
        uint32_t ah[2][4], al[2][4];
#pragma unroll
        for (int mi = 0; mi < 2; mi++) {
            ldsm4(ah[mi], sAhi + aoff + mi*(16*LDQB) + ko);
            ldsm4(al[mi], sAlo + aoff + mi*(16*LDQB) + ko);
        }
#pragma unroll
        for (int bt = 0; bt < 4; bt++) {
            uint32_t bh[4], bl[4];
            ldsm4(bh, sBhi + boff + bt*(16*LDQB) + ko);
            ldsm4(bl, sBlo + boff + bt*(16*LDQB) + ko);
#pragma unroll
            for (int ch = 0; ch < 2; ch++) {
                uint32_t b2h[2] = {bh[ch], bh[ch+2]};
                uint32_t b2l[2] = {bl[ch], bl[ch+2]};
#pragma unroll
                for (int mi = 0; mi < 2; mi++) {
                    mma16816(C[mi][bt*2+ch], ah[mi], b2h);   // hi*hi
                    mma16816(C[mi][bt*2+ch], ah[mi], b2l);   // hi*lo
                    mma16816(C[mi][bt*2+ch], al[mi], b2h);   // lo*hi
                }
            }
        }
    }
}

__global__ __launch_bounds__(256, 1)
void aggregate_mma(const __nv_bfloat16* __restrict__ nhh, const __nv_bfloat16* __restrict__ nhl,
                   const __nv_bfloat16* __restrict__ hth, const __nv_bfloat16* __restrict__ htl,
                   const float* __restrict__ ew, float* __restrict__ out, int do_relu) {
    extern __shared__ char smraw[];
    char* smc = smraw;
    const uint32_t sb = smem_to_u32(smc);
    const int tid = threadIdx.x;
    const int warp = tid >> 5, lane = tid & 31;
    const int wm = warp >> 1, wn = warp & 1;
    const int g = lane >> 2, t = lane & 3;
    const int b = blockIdx.y;
    const int pbase = blockIdx.x * 128;

    // persistent A1: nh p-tile hi/lo
    g2s_tile(nhh + ((size_t)b*NN + pbase)*DD, DD, smc + SA1H, tid);
    g2s_tile(nhl + ((size_t)b*NN + pbase)*DD, DD, smc + SA1L, tid);

    float outC[2][8][4] = {};

    for (int qt = 0; qt < 16; qt++) {
        const int qbase = qt * 128;
        if (qt) __syncthreads();   // MMA2 of previous iter done reading S'/B2
        g2s_tile(nhh + ((size_t)b*NN + qbase)*DD, DD, smc + SB1H, tid);
        g2s_tile(nhl + ((size_t)b*NN + qbase)*DD, DD, smc + SB1L, tid);
        g2s_tile(hth + (size_t)b*DD*NN + qbase, NN, smc + SB2H, tid);
        g2s_tile(htl + (size_t)b*DD*NN + qbase, NN, smc + SB2L, tid);
        __syncthreads();

        // ---- MMA1: S = nh_p . nh_q^T ----
        float sC[2][8][4] = {};
        mma_phase(sb + SA1H, sb + SA1L, sb + SB1H, sb + SB1L, sC, wm, wn, lane);

        // ---- scale by edge weight (fragment-mapped gmem loads) ----
#pragma unroll
        for (int mi = 0; mi < 2; mi++) {
            const int p0 = wm*32 + mi*16 + g;
            const float* e0 = ew + ((size_t)b*NN + pbase + p0)*NN + qbase + wn*64 + 2*t;
            const float* e1 = e0 + (size_t)8*NN;
#pragma unroll
            for (int ni = 0; ni < 8; ni++) {
                float2 w0 = *(const float2*)(e0 + ni*8);
                float2 w1 = *(const float2*)(e1 + ni*8);
                sC[mi][ni][0] *= w0.x; sC[mi][ni][1] *= w0.y;
                sC[mi][ni][2] *= w1.x; sC[mi][ni][3] *= w1.y;
            }
        }
        __syncthreads();   // everyone done reading B1 before S' overwrites it

        // ---- pack S' to bf16 hi/lo, store into B1 region ----
#pragma unroll
        for (int mi = 0; mi < 2; mi++) {
            const int p0 = wm*32 + mi*16 + g;
#pragma unroll
            for (int ni = 0; ni < 8; ni++) {
                const int q = wn*64 + ni*8 + 2*t;
                uint32_t h0 = pack_hi(sC[mi][ni][0], sC[mi][ni][1]);
                uint32_t l0 = pack_lo(sC[mi][ni][0], sC[mi][ni][1], h0);
                uint32_t h1 = pack_hi(sC[mi][ni][2], sC[mi][ni][3]);
                uint32_t l1 = pack_lo(sC[mi][ni][2], sC[mi][ni][3], h1);
                *(uint32_t*)(smc + SB1H + p0*LDQB + q*2)     = h0;
                *(uint32_t*)(smc + SB1L + p0*LDQB + q*2)     = l0;
                *(uint32_t*)(smc + SB1H + (p0+8)*LDQB + q*2) = h1;
                *(uint32_t*)(smc + SB1L + (p0+8)*LDQB + q*2) = l1;
            }
        }
        __syncthreads();

        // ---- MMA2: out += S' . hT^T (accumulate across q-tiles) ----
        mma_phase(sb + SB1H, sb + SB1L, sb + SB2H, sb + SB2L, outC, wm, wn, lane);
    }

    // ---- epilogue: store out (+relu) ----
#pragma unroll
    for (int mi = 0; mi < 2; mi++) {
        const int p0 = pbase + wm*32 + mi*16 + g;
        float* r0 = out + ((size_t)b*NN + p0)*DD;
        float* r1 = r0 + (size_t)8*DD;
#pragma unroll
        for (int ni = 0; ni < 8; ni++) {
            const int c = wn*64 + ni*8 + 2*t;
            float d0 = outC[mi][ni][0], d1 = outC[mi][ni][1];
            float d2 = outC[mi][ni][2], d3 = outC[mi][ni][3];
            if (do_relu) {
                d0 = fmaxf(d0, 0.f); d1 = fmaxf(d1, 0.f);
                d2 = fmaxf(d2, 0.f); d3 = fmaxf(d3, 0.f);
            }
            *(float2*)(r0 + c) = make_float2(d0, d1);
            *(float2*)(r1 + c) = make_float2(d2, d3);
        }
    }
}

// ---------------------------------------------------------------------------
extern "C" void kernel_launch(void* const* d_in, const int* in_sizes, int n_in,
                              void* d_out, int out_size) {
    const float* x  = (const float*)d_in[0];
    const float* ew = (const float*)d_in[1];
    const float* Wl[3] = {(const float*)d_in[2], (const float*)d_in[4], (const float*)d_in[6]};
    const float* bl[3] = {(const float*)d_in[3], (const float*)d_in[5], (const float*)d_in[7]};
    float* out = (float*)d_out;

    float *lin, *buf;
    __nv_bfloat16 *nhh, *nhl, *hth, *htl;
    cudaGetSymbolAddress((void**)&lin, g_lin);
    cudaGetSymbolAddress((void**)&buf, g_buf);
    cudaGetSymbolAddress((void**)&nhh, g_nh_hi);
    cudaGetSymbolAddress((void**)&nhl, g_nh_lo);
    cudaGetSymbolAddress((void**)&hth, g_ht_hi);
    cudaGetSymbolAddress((void**)&htl, g_ht_lo);

    (void)cudaFuncSetAttribute(linear_kernel,
        cudaFuncAttributeMaxDynamicSharedMemorySize, (DD*DD + 64*DD)*4);
    (void)cudaFuncSetAttribute(aggregate_mma,
        cudaFuncAttributeMaxDynamicSharedMemorySize, SM_AGG);

    dim3 blk(16, 16);
    for (int l = 0; l < 3; l++) {
        const float* in = (l == 0) ? x : buf;
        linear_kernel<<<BB*NN/64, blk, (DD*DD + 64*DD)*4>>>(in, Wl[l], bl[l], lin);
        normalize_convert<<<BB*NN/8, 256>>>(lin, nhh, nhl, hth, htl);
        float* o = (l == 2) ? out : buf;
        aggregate_mma<<<dim3(NN/128, BB), 256, SM_AGG>>>(
            nhh, nhl, hth, htl, ew, o, (l < 2) ? 1 : 0);
    }
}

// round 14
// speedup vs baseline: 5.7892x; 1.2467x over previous
#include <cuda_runtime.h>
#include <cuda_bf16.h>
#include <cstdint>

#define BB 8
#define NN 2048
#define DD 128

// ---------------- scratch (__device__ globals; allocation-free rule) -------
__device__ __align__(256) float g_lin[BB*NN*DD];            // post-linear h
__device__ __align__(256) float g_buf[BB*NN*DD];            // layer output
__device__ __align__(256) float g_nrm[BB*NN];               // ||h|| (clamped)
__device__ __align__(256) __nv_bfloat16 g_nh_hi[BB*NN*DD];  // normalized h, hi
__device__ __align__(256) __nv_bfloat16 g_nh_lo[BB*NN*DD];  // normalized h, lo
__device__ __align__(256) __nv_bfloat16 g_nt_hi[BB*DD*NN];  // nh transposed [b][c][q], hi
__device__ __align__(256) __nv_bfloat16 g_nt_lo[BB*DD*NN];  // nh transposed [b][c][q], lo

// ---------------- helpers --------------------------------------------------
__device__ __forceinline__ uint32_t smem_to_u32(const void* p) {
    uint32_t a;
    asm("{ .reg .u64 t; cvta.to.shared.u64 t, %1; cvt.u32.u64 %0, t; }"
        : "=r"(a) : "l"(p));
    return a;
}
__device__ __forceinline__ void ldsm4(uint32_t* r, uint32_t addr) {
    asm volatile("ldmatrix.sync.aligned.m8n8.x4.shared.b16 {%0,%1,%2,%3}, [%4];"
        : "=r"(r[0]), "=r"(r[1]), "=r"(r[2]), "=r"(r[3]) : "r"(addr));
}
__device__ __forceinline__ void ldsm4t(uint32_t* r, uint32_t addr) {
    asm volatile("ldmatrix.sync.aligned.m8n8.x4.trans.shared.b16 {%0,%1,%2,%3}, [%4];"
        : "=r"(r[0]), "=r"(r[1]), "=r"(r[2]), "=r"(r[3]) : "r"(addr));
}
__device__ __forceinline__ void mma16816(float* d, const uint32_t* a, const uint32_t* b) {
    asm volatile("mma.sync.aligned.m16n8k16.row.col.f32.bf16.bf16.f32 "
        "{%0,%1,%2,%3}, {%4,%5,%6,%7}, {%8,%9}, {%0,%1,%2,%3};"
        : "+f"(d[0]), "+f"(d[1]), "+f"(d[2]), "+f"(d[3])
        : "r"(a[0]), "r"(a[1]), "r"(a[2]), "r"(a[3]), "r"(b[0]), "r"(b[1]));
}
__device__ __forceinline__ uint32_t pack_hi(float f0, float f1) {
    uint32_t r;
    asm("cvt.rn.bf16x2.f32 %0, %1, %2;" : "=r"(r) : "f"(f1), "f"(f0));
    return r;
}
__device__ __forceinline__ uint32_t pack_lo(float f0, float f1, uint32_t h) {
    float g0 = __uint_as_float(h << 16);
    float g1 = __uint_as_float(h & 0xffff0000u);
    uint32_t r;
    asm("cvt.rn.bf16x2.f32 %0, %1, %2;" : "=r"(r) : "f"(f1 - g1), "f"(f0 - g0));
    return r;
}
__device__ __forceinline__ void cp_async16(uint32_t saddr, const void* gaddr) {
    asm volatile("cp.async.cg.shared.global [%0], [%1], 16;"
        :: "r"(saddr), "l"(gaddr) : "memory");
}
__device__ __forceinline__ void cp_commit() {
    asm volatile("cp.async.commit_group;" ::: "memory");
}
__device__ __forceinline__ void cp_wait_all() {
    asm volatile("cp.async.wait_group 0;" ::: "memory");
}

// ---------------------------------------------------------------------------
// Linear: out[r][c] = sum_k in[r][k]*W[k][c] + b[c]
// ---------------------------------------------------------------------------
__global__ __launch_bounds__(256, 2)
void linear_kernel(const float* __restrict__ in, const float* __restrict__ W,
                   const float* __restrict__ bias, float* __restrict__ out) {
    extern __shared__ char smraw[];
    float* smf = (float*)smraw;
    float* sW = smf;
    float* sX = smf + DD*DD;
    const int tx = threadIdx.x, ty = threadIdx.y;
    const int tid = ty*16 + tx;
    const int rowbase = blockIdx.x * 64;

    const float4* W4 = (const float4*)W;
    float4* sW4 = (float4*)sW;
#pragma unroll
    for (int i = 0; i < 16; i++) sW4[tid + i*256] = W4[tid + i*256];
    const float4* X4 = (const float4*)(in + (size_t)rowbase*DD);
    float4* sX4 = (float4*)sX;
#pragma unroll
    for (int i = 0; i < 8; i++) sX4[tid + i*256] = X4[tid + i*256];
    __syncthreads();

    float acc[4][8];
#pragma unroll
    for (int j = 0; j < 4; j++)
#pragma unroll
        for (int c = 0; c < 8; c++) acc[j][c] = 0.0f;

#pragma unroll 8
    for (int k = 0; k < DD; k++) {
        float4 w0 = *(const float4*)&sW[k*DD + tx*8];
        float4 w1 = *(const float4*)&sW[k*DD + tx*8 + 4];
#pragma unroll
        for (int j = 0; j < 4; j++) {
            float a = sX[(ty*4+j)*DD + k];
            acc[j][0] += a*w0.x; acc[j][1] += a*w0.y;
            acc[j][2] += a*w0.z; acc[j][3] += a*w0.w;
            acc[j][4] += a*w1.x; acc[j][5] += a*w1.y;
            acc[j][6] += a*w1.z; acc[j][7] += a*w1.w;
        }
    }
    float4 bv0 = *(const float4*)&bias[tx*8];
    float4 bv1 = *(const float4*)&bias[tx*8 + 4];
#pragma unroll
    for (int j = 0; j < 4; j++) {
        int row = rowbase + ty*4 + j;
        *(float4*)&out[(size_t)row*DD + tx*8] =
            make_float4(acc[j][0]+bv0.x, acc[j][1]+bv0.y, acc[j][2]+bv0.z, acc[j][3]+bv0.w);
        *(float4*)&out[(size_t)row*DD + tx*8 + 4] =
            make_float4(acc[j][4]+bv1.x, acc[j][5]+bv1.y, acc[j][6]+bv1.z, acc[j][7]+bv1.w);
    }
}

// ---------------------------------------------------------------------------
// normalize_convert: nh = h/max(||h||,eps) as bf16 hi/lo (row-major),
// nh transposed [b][c][q] as bf16 hi/lo, and nrm = max(||h||,eps).
// ---------------------------------------------------------------------------
__global__ __launch_bounds__(256, 4)
void normalize_convert(const float* __restrict__ h,
                       __nv_bfloat16* __restrict__ nhh, __nv_bfloat16* __restrict__ nhl,
                       __nv_bfloat16* __restrict__ nth, __nv_bfloat16* __restrict__ ntl,
                       float* __restrict__ nrm) {
    __shared__ uint32_t sh[8*64], sl[8*64];   // 8 rows x 128 bf16 (as u32 pairs)
    const int tid = threadIdx.x;
    const int w = tid >> 5, lane = tid & 31;
    const size_t rowbase = (size_t)blockIdx.x * 8;
    const size_t row = rowbase + w;

    float4 x = *(const float4*)(h + row*DD + lane*4);
    float ss = x.x*x.x + x.y*x.y + x.z*x.z + x.w*x.w;
#pragma unroll
    for (int o = 16; o; o >>= 1) ss += __shfl_xor_sync(0xffffffffu, ss, o);
    float eff = fmaxf(sqrtf(ss), 1e-12f);
    float inv = 1.0f / eff;
    if (lane == 0) nrm[row] = eff;

    float n0 = x.x*inv, n1 = x.y*inv, n2 = x.z*inv, n3 = x.w*inv;
    uint32_t nha = pack_hi(n0, n1), nhb = pack_hi(n2, n3);
    uint32_t nla = pack_lo(n0, n1, nha), nlb = pack_lo(n2, n3, nhb);
    *(uint2*)(nhh + row*DD + lane*4) = make_uint2(nha, nhb);
    *(uint2*)(nhl + row*DD + lane*4) = make_uint2(nla, nlb);

    sh[w*64 + lane*2] = nha; sh[w*64 + lane*2 + 1] = nhb;
    sl[w*64 + lane*2] = nla; sl[w*64 + lane*2 + 1] = nlb;
    __syncthreads();

    const int c = tid & 127, which = tid >> 7;
    const unsigned short* s = (const unsigned short*)(which ? sl : sh);
    uint32_t p0 = (uint32_t)s[0*128 + c] | ((uint32_t)s[1*128 + c] << 16);
    uint32_t p1 = (uint32_t)s[2*128 + c] | ((uint32_t)s[3*128 + c] << 16);
    uint32_t p2 = (uint32_t)s[4*128 + c] | ((uint32_t)s[5*128 + c] << 16);
    uint32_t p3 = (uint32_t)s[6*128 + c] | ((uint32_t)s[7*128 + c] << 16);
    const size_t b = rowbase / NN, q0 = rowbase % NN;
    __nv_bfloat16* dst = which ? ntl : nth;
    *(uint4*)(dst + (b*DD + c)*NN + q0) = make_uint4(p0, p1, p2, p3);
}

// ---------------------------------------------------------------------------
// aggregate_mma: out[p][c] = sum_q ew[p][q] * (nh_p . nh_q) * nrm_q * nh[q][c]
// Single nhT q-tile serves MMA1 (via ldmatrix.trans) and MMA2 (non-trans).
// S' stays in registers (C-frag == A-frag layout). cp.async double buffering.
// ---------------------------------------------------------------------------
#define LDQB 272                       // bytes per smem row (128 bf16 + pad)
#define TILEB 34816                    // 128 * LDQB
#define SA1H 0                         // persistent nh p-tile hi
#define SA1L TILEB                     //                      lo
#define SQ0  (2*TILEB)                 // q nhT buf0 (hi, lo at +TILEB)
#define SQ1  (4*TILEB)                 // q nhT buf1
#define SM_AGG (6*TILEB)               // 208896 bytes

__global__ __launch_bounds__(256, 1)
void aggregate_mma(const __nv_bfloat16* __restrict__ nhh, const __nv_bfloat16* __restrict__ nhl,
                   const __nv_bfloat16* __restrict__ nth, const __nv_bfloat16* __restrict__ ntl,
                   const float* __restrict__ nrm, const float* __restrict__ ew,
                   float* __restrict__ out, int do_relu) {
    extern __shared__ char smraw[];
    const uint32_t sb = smem_to_u32(smraw);
    const int tid = threadIdx.x;
    const int warp = tid >> 5, lane = tid & 31;
    const int g = lane >> 2, t = lane & 3;
    const int b = blockIdx.y;
    const int pbase = blockIdx.x * 128;

    // prologue: cp.async A1 (nh p-tile hi/lo) + q-tile 0
    {
        const __nv_bfloat16* ah = nhh + ((size_t)b*NN + pbase)*DD;
        const __nv_bfloat16* al = nhl + ((size_t)b*NN + pbase)*DD;
#pragma unroll
        for (int i = 0; i < 8; i++) {
            int idx = tid + i*256, row = idx >> 4, u = idx & 15;
            cp_async16(sb + SA1H + row*LDQB + u*16, ah + (size_t)row*DD + u*8);
            cp_async16(sb + SA1L + row*LDQB + u*16, al + (size_t)row*DD + u*8);
        }
        const __nv_bfloat16* qh = nth + (size_t)b*DD*NN;
        const __nv_bfloat16* ql = ntl + (size_t)b*DD*NN;
#pragma unroll
        for (int i = 0; i < 8; i++) {
            int idx = tid + i*256, row = idx >> 4, u = idx & 15;
            cp_async16(sb + SQ0 + row*LDQB + u*16,         qh + (size_t)row*NN + u*8);
            cp_async16(sb + SQ0 + TILEB + row*LDQB + u*16, ql + (size_t)row*NN + u*8);
        }
        cp_commit();
    }

    const uint32_t aoff = (uint32_t)((warp*16 + (lane & 15))*LDQB + (lane >> 4)*16);
    const uint32_t qoff = (uint32_t)((lane & 15)*LDQB + (lane >> 4)*16);
    const int prow = pbase + warp*16 + g;
    const float* ew0 = ew + ((size_t)b*NN + prow)*NN;
    const float* ew1 = ew0 + (size_t)8*NN;
    const float* nrmb = nrm + (size_t)b*NN;

    float outC[16][4] = {};

    for (int qt = 0; qt < 16; qt++) {
        cp_wait_all();
        __syncthreads();   // buffer visible; all warps done with buffer being refilled

        // prefetch next q-tile into the other buffer (overlaps compute)
        if (qt < 15) {
            const int nb = (qt + 1) & 1;
            const uint32_t sdst = sb + (nb ? SQ1 : SQ0);
            const __nv_bfloat16* qh = nth + (size_t)b*DD*NN + (qt+1)*128;
            const __nv_bfloat16* ql = ntl + (size_t)b*DD*NN + (qt+1)*128;
#pragma unroll
            for (int i = 0; i < 8; i++) {
                int idx = tid + i*256, row = idx >> 4, u = idx & 15;
                cp_async16(sdst + row*LDQB + u*16,         qh + (size_t)row*NN + u*8);
                cp_async16(sdst + TILEB + row*LDQB + u*16, ql + (size_t)row*NN + u*8);
            }
            cp_commit();
        }

        const uint32_t sq = sb + ((qt & 1) ? SQ1 : SQ0);

        // ---- MMA1: S[m16][q128] = nh_p . nh_q^T (3-product split bf16) ----
        float sC[16][4] = {};
#pragma unroll
        for (int ks = 0; ks < 8; ks++) {
            uint32_t ah[4], al[4];
            ldsm4(ah, sb + SA1H + aoff + ks*32);
            ldsm4(al, sb + SA1L + aoff + ks*32);
            const uint32_t rowb = sq + (uint32_t)(ks*16*LDQB) + qoff;
#pragma unroll
            for (int nt = 0; nt < 8; nt++) {
                uint32_t bh[4], bl[4];
                ldsm4t(bh, rowb + nt*32);
                ldsm4t(bl, rowb + TILEB + nt*32);
#pragma unroll
                for (int sub = 0; sub < 2; sub++) {
                    uint32_t b2h[2] = {bh[sub*2], bh[sub*2+1]};
                    uint32_t b2l[2] = {bl[sub*2], bl[sub*2+1]};
                    float* C = sC[nt*2 + sub];
                    mma16816(C, ah, b2h);
                    mma16816(C, ah, b2l);
                    mma16816(C, al, b2h);
                }
            }
        }

        // ---- scale: S' = S * ew * nrm_q ----
        const int qb = qt * 128;
#pragma unroll
        for (int j = 0; j < 16; j++) {
            const int q = qb + j*8 + 2*t;
            float2 nq = *(const float2*)(nrmb + q);
            float2 e0 = *(const float2*)(ew0 + q);
            float2 e1 = *(const float2*)(ew1 + q);
            sC[j][0] *= e0.x * nq.x; sC[j][1] *= e0.y * nq.y;
            sC[j][2] *= e1.x * nq.x; sC[j][3] *= e1.y * nq.y;
        }

        // ---- MMA2: out[m16][c128] += S' . nhT (A from registers) ----
#pragma unroll
        for (int s = 0; s < 8; s++) {
            uint32_t ah2[4], al2[4];
            ah2[0] = pack_hi(sC[2*s][0],   sC[2*s][1]);
            ah2[1] = pack_hi(sC[2*s][2],   sC[2*s][3]);
            ah2[2] = pack_hi(sC[2*s+1][0], sC[2*s+1][1]);
            ah2[3] = pack_hi(sC[2*s+1][2], sC[2*s+1][3]);
            al2[0] = pack_lo(sC[2*s][0],   sC[2*s][1],   ah2[0]);
            al2[1] = pack_lo(sC[2*s][2],   sC[2*s][3],   ah2[1]);
            al2[2] = pack_lo(sC[2*s+1][0], sC[2*s+1][1], ah2[2]);
            al2[3] = pack_lo(sC[2*s+1][2], sC[2*s+1][3], ah2[3]);
            const uint32_t cb = sq + qoff + (uint32_t)(s*32);
#pragma unroll
            for (int ct = 0; ct < 8; ct++) {
                uint32_t bh[4], bl[4];
                ldsm4(bh, cb + ct*(16*LDQB));
                ldsm4(bl, cb + TILEB + ct*(16*LDQB));
#pragma unroll
                for (int ch = 0; ch < 2; ch++) {
                    uint32_t b2h[2] = {bh[ch], bh[ch+2]};
                    uint32_t b2l[2] = {bl[ch], bl[ch+2]};
                    float* C = outC[ct*2 + ch];
                    mma16816(C, ah2, b2h);
                    mma16816(C, ah2, b2l);
                    mma16816(C, al2, b2h);
                }
            }
        }
        __syncthreads();   // all warps done reading sq before it is refilled
    }

    // ---- epilogue: store out (+relu) ----
    float* r0 = out + ((size_t)b*NN + prow)*DD;
    float* r1 = r0 + (size_t)8*DD;
#pragma unroll
    for (int j = 0; j < 16; j++) {
        const int c = j*8 + 2*t;
        float d0 = outC[j][0], d1 = outC[j][1];
        float d2 = outC[j][2], d3 = outC[j][3];
        if (do_relu) {
            d0 = fmaxf(d0, 0.f); d1 = fmaxf(d1, 0.f);
            d2 = fmaxf(d2, 0.f); d3 = fmaxf(d3, 0.f);
        }
        *(float2*)(r0 + c) = make_float2(d0, d1);
        *(float2*)(r1 + c) = make_float2(d2, d3);
    }
}

// ---------------------------------------------------------------------------
extern "C" void kernel_launch(void* const* d_in, const int* in_sizes, int n_in,
                              void* d_out, int out_size) {
    const float* x  = (const float*)d_in[0];
    const float* ew = (const float*)d_in[1];
    const float* Wl[3] = {(const float*)d_in[2], (const float*)d_in[4], (const float*)d_in[6]};
    const float* bl[3] = {(const float*)d_in[3], (const float*)d_in[5], (const float*)d_in[7]};
    float* out = (float*)d_out;

    float *lin, *buf, *nrm;
    __nv_bfloat16 *nhh, *nhl, *nth, *ntl;
    cudaGetSymbolAddress((void**)&lin, g_lin);
    cudaGetSymbolAddress((void**)&buf, g_buf);
    cudaGetSymbolAddress((void**)&nrm, g_nrm);
    cudaGetSymbolAddress((void**)&nhh, g_nh_hi);
    cudaGetSymbolAddress((void**)&nhl, g_nh_lo);
    cudaGetSymbolAddress((void**)&nth, g_nt_hi);
    cudaGetSymbolAddress((void**)&ntl, g_nt_lo);

    (void)cudaFuncSetAttribute(linear_kernel,
        cudaFuncAttributeMaxDynamicSharedMemorySize, (DD*DD + 64*DD)*4);
    (void)cudaFuncSetAttribute(aggregate_mma,
        cudaFuncAttributeMaxDynamicSharedMemorySize, SM_AGG);

    dim3 blk(16, 16);
    for (int l = 0; l < 3; l++) {
        const float* in = (l == 0) ? x : buf;
        linear_kernel<<<BB*NN/64, blk, (DD*DD + 64*DD)*4>>>(in, Wl[l], bl[l], lin);
        normalize_convert<<<BB*NN/8, 256>>>(lin, nhh, nhl, nth, ntl, nrm);
        float* o = (l == 2) ? out : buf;
        aggregate_mma<<<dim3(NN/128, BB), 256, SM_AGG>>>(
            nhh, nhl, nth, ntl, nrm, ew, o, (l < 2) ? 1 : 0);
    }
}